// round 1
// baseline (speedup 1.0000x reference)
#include <cuda_runtime.h>

// BatchDelayProcessor: lag-D feedback delay line.
//   c_k = x_k + FB * c_{k-1}         (carry per chain, c_{-1} = 0)
//   out_k = (1-MIX) * x_k + MIX * c_{k-1}
// Each (b, j) with j in [0, D) is an independent length-NBLK chain.

#define D_SAMP   22050
#define T_LEN    441000
#define B_SZ     64
#define NBLK     20          // T_LEN / D_SAMP
#define FB       0.3f
#define MIXC     0.5f

// float2 vectorization: D_SAMP % 2 == 0
#define HD       (D_SAMP / 2)                 // 11025 float2 chains per batch row
#define NCHAINS  ((long long)B_SZ * HD)       // 705600

__global__ __launch_bounds__(256) void delay_kernel(const float* __restrict__ x,
                                                    float* __restrict__ out) {
    long long idx = (long long)blockIdx.x * blockDim.x + threadIdx.x;
    if (idx >= NCHAINS) return;

    int b = (int)(idx / HD);
    int j = (int)(idx % HD) * 2;

    const char* xbase = (const char*)(x + (size_t)b * T_LEN + j);
    char*       obase = (char*)(out + (size_t)b * T_LEN + j);

    float2 c;
    c.x = 0.0f;
    c.y = 0.0f;

    const size_t blk_stride = (size_t)D_SAMP * sizeof(float);  // 88200 B

#pragma unroll
    for (int k = 0; k < NBLK; k++) {
        float2 xv = *reinterpret_cast<const float2*>(xbase + (size_t)k * blk_stride);
        float2 o;
        // out = x*(1-MIX) + c*MIX
        o.x = fmaf(c.x, MIXC, xv.x * (1.0f - MIXC));
        o.y = fmaf(c.y, MIXC, xv.y * (1.0f - MIXC));
        *reinterpret_cast<float2*>(obase + (size_t)k * blk_stride) = o;
        // c = x + FB*c
        c.x = fmaf(c.x, FB, xv.x);
        c.y = fmaf(c.y, FB, xv.y);
    }
}

extern "C" void kernel_launch(void* const* d_in, const int* in_sizes, int n_in,
                              void* d_out, int out_size) {
    const float* x = (const float*)d_in[0];
    float* out = (float*)d_out;

    const int threads = 256;
    const long long nthreads = NCHAINS;
    const int blocks = (int)((nthreads + threads - 1) / threads);
    delay_kernel<<<blocks, threads>>>(x, out);
}